// round 8
// baseline (speedup 1.0000x reference)
#include <cuda_runtime.h>
#include <cuda_bf16.h>
#include <cstdint>

// MHC fused: persistent work-stealing, L2-prefetch depth 2, mix-before-barrier.
// grid = #SMs, 1 CTA/SM, 512 threads. Atomic ticket (self-resetting for graph
// replay). Per iteration: prefetch row r+2 into L2, load row r (L2 hits),
// compute mix=P*x and agg BEFORE the reduce barrier; post-barrier path is
// just out = mix + (hpost*rinv)*t -> stores launch early.

#define NS        4
#define CDIM      4096
#define C4        (CDIM / 4)
#define THREADS   512
#define NWARPS    (THREADS / 32)
#define EPSF      1e-6f
#define SINKITERS 3
#define ROW_BYTES (NS * CDIM * 4)   // 65536 = 512 threads * 128B

__device__ int g_ticket = 0;
__device__ int g_done   = 0;

__device__ __forceinline__ void pf_l2(const void* p) {
    asm volatile("prefetch.global.L2 [%0];" :: "l"(p));
}

__global__ __launch_bounds__(THREADS, 1)
void mhc_ws2_kernel(const float* __restrict__ x,
                    const float* __restrict__ w,
                    const float* __restrict__ Hpre,
                    const float* __restrict__ Hpost,
                    const float* __restrict__ Hres,
                    float* __restrict__ out, int B)
{
    __shared__ float ps[24];                 // hpre[4], hpost[4], P[16]
    __shared__ float wsum[2][NWARPS];
    __shared__ int   nrow[3];                // [0],[1] parity slots; [2] init

    const int tid = threadIdx.x, lane = tid & 31, wid = tid >> 5;

    // ---- Warp 0: tiny params once (sigmoids + Sinkhorn) -> smem ----
    if (wid == 0) {
        float hpre[NS], hpost[NS], P[NS][NS];
        #pragma unroll
        for (int i = 0; i < NS; i++) {
            hpre[i]  = 1.0f / (1.0f + expf(-Hpre[i]));
            hpost[i] = 2.0f / (1.0f + expf(-Hpost[i]));
        }
        #pragma unroll
        for (int i = 0; i < NS; i++)
            #pragma unroll
            for (int j = 0; j < NS; j++)
                P[i][j] = expf(Hres[i * NS + j]);
        #pragma unroll
        for (int it = 0; it < SINKITERS; it++) {
            #pragma unroll
            for (int i = 0; i < NS; i++) {
                float ri = 1.0f / (P[i][0] + P[i][1] + P[i][2] + P[i][3] + EPSF);
                #pragma unroll
                for (int j = 0; j < NS; j++) P[i][j] *= ri;
            }
            #pragma unroll
            for (int j = 0; j < NS; j++) {
                float ci = 1.0f / (P[0][j] + P[1][j] + P[2][j] + P[3][j] + EPSF);
                #pragma unroll
                for (int i = 0; i < NS; i++) P[i][j] *= ci;
            }
        }
        if (lane == 0) {
            #pragma unroll
            for (int i = 0; i < NS; i++) { ps[i] = hpre[i]; ps[4 + i] = hpost[i]; }
            #pragma unroll
            for (int i = 0; i < NS; i++)
                #pragma unroll
                for (int j = 0; j < NS; j++)
                    ps[8 + i * NS + j] = P[i][j];
        }
    }

    // ---- Grab first three rows (prefetch pipeline depth 2) ----
    if (tid == 0) {
        nrow[0] = atomicAdd(&g_ticket, 1);
        nrow[1] = atomicAdd(&g_ticket, 1);
        nrow[2] = atomicAdd(&g_ticket, 1);
    }
    __syncthreads();

    // Loop-invariant params in registers
    const float h0 = ps[0], h1 = ps[1], h2 = ps[2], h3 = ps[3];
    float Pr[NS][NS], hp[NS];
    #pragma unroll
    for (int i = 0; i < NS; i++) {
        hp[i] = ps[4 + i];
        #pragma unroll
        for (int j = 0; j < NS; j++) Pr[i][j] = ps[8 + i * NS + j];
    }
    const float4 wv0 = __ldg(reinterpret_cast<const float4*>(w) + tid);
    const float4 wv1 = __ldg(reinterpret_cast<const float4*>(w) + tid + THREADS);
    const float wa[8] = {wv0.x, wv0.y, wv0.z, wv0.w,
                         wv1.x, wv1.y, wv1.z, wv1.w};

    const char* __restrict__ xb = reinterpret_cast<const char*>(x);
    int cur = nrow[0], nxt = nrow[1], nx2 = nrow[2];

    // Warm L2 with the first two rows
    if (cur < B) pf_l2(xb + (size_t)cur * ROW_BYTES + tid * 128);
    if (nxt < B) pf_l2(xb + (size_t)nxt * ROW_BYTES + tid * 128);

    int k = 0;
    while (cur < B) {
        // ---- Prefetch row r+2 into L2 ----
        if (nx2 < B)
            pf_l2(xb + (size_t)nx2 * ROW_BYTES + tid * 128);

        // ---- Front-batched loads of current row, evict-first ----
        const float4* __restrict__ xr =
            reinterpret_cast<const float4*>(xb + (size_t)cur * ROW_BYTES);
        float4 v4[NS][2];
        #pragma unroll
        for (int n = 0; n < NS; n++) {
            v4[n][0] = __ldcs(&xr[n * C4 + tid]);
            v4[n][1] = __ldcs(&xr[n * C4 + tid + THREADS]);
        }

        // ---- Next ticket (published by this iteration's barrier) ----
        if (tid == 0) nrow[k & 1] = atomicAdd(&g_ticket, 1);

        // ---- Pre-barrier compute: agg, t, AND the full P-mix ----
        float mix[NS][8];
        float agg[8];
        float ss = 0.0f;
        #pragma unroll
        for (int n = 0; n < NS; n++) {
            float xe[8] = {v4[n][0].x, v4[n][0].y, v4[n][0].z, v4[n][0].w,
                           v4[n][1].x, v4[n][1].y, v4[n][1].z, v4[n][1].w};
            #pragma unroll
            for (int e = 0; e < 8; e++) {
                if (n == 0) {
                    mix[0][e] = Pr[0][0] * xe[e];
                    mix[1][e] = Pr[1][0] * xe[e];
                    mix[2][e] = Pr[2][0] * xe[e];
                    mix[3][e] = Pr[3][0] * xe[e];
                    agg[e]    = h0 * xe[e];
                } else {
                    const float hn = (n == 1) ? h1 : (n == 2) ? h2 : h3;
                    mix[0][e] += Pr[0][n] * xe[e];
                    mix[1][e] += Pr[1][n] * xe[e];
                    mix[2][e] += Pr[2][n] * xe[e];
                    mix[3][e] += Pr[3][n] * xe[e];
                    agg[e]    += hn * xe[e];
                }
            }
        }
        float t[8];
        #pragma unroll
        for (int e = 0; e < 8; e++) {
            float a = __bfloat162float(__float2bfloat16_rn(agg[e]));
            ss += a * a;
            t[e] = a * wa[e];
        }

        // ---- Block reduce (single barrier, parity slots) ----
        #pragma unroll
        for (int o = 16; o > 0; o >>= 1)
            ss += __shfl_xor_sync(0xffffffffu, ss, o);
        if (lane == 0) wsum[k & 1][wid] = ss;
        __syncthreads();
        float tot = 0.0f;
        #pragma unroll
        for (int i = 0; i < NWARPS; i++) tot += wsum[k & 1][i];
        const float rinv = rsqrtf(tot * (1.0f / CDIM) + EPSF);
        const int nn = nrow[k & 1];

        // ---- Short post-barrier path: out = mix + h*t; streaming stores ----
        float4* __restrict__ orow =
            reinterpret_cast<float4*>(out) + (size_t)cur * (NS * C4);
        #pragma unroll
        for (int i = 0; i < NS; i++) {
            const float h = hp[i] * rinv;
            float4 o0, o1;
            o0.x = mix[i][0] + h * t[0];
            o0.y = mix[i][1] + h * t[1];
            o0.z = mix[i][2] + h * t[2];
            o0.w = mix[i][3] + h * t[3];
            o1.x = mix[i][4] + h * t[4];
            o1.y = mix[i][5] + h * t[5];
            o1.z = mix[i][6] + h * t[6];
            o1.w = mix[i][7] + h * t[7];
            __stcs(&orow[i * C4 + tid], o0);
            __stcs(&orow[i * C4 + tid + THREADS], o1);
        }

        cur = nxt; nxt = nx2; nx2 = nn; k++;
    }

    // ---- Self-reset for graph replay ----
    if (tid == 0) {
        int d = atomicAdd(&g_done, 1);
        if (d == (int)gridDim.x - 1) {
            g_ticket = 0;
            g_done   = 0;
        }
    }
}

extern "C" void kernel_launch(void* const* d_in, const int* in_sizes, int n_in,
                              void* d_out, int out_size)
{
    const float* x      = (const float*)d_in[0];
    const float* w      = (const float*)d_in[1];
    const float* H_pre  = (const float*)d_in[2];
    const float* H_post = (const float*)d_in[3];
    const float* H_res  = (const float*)d_in[4];
    float* out          = (float*)d_out;

    const int B = in_sizes[0] / (NS * CDIM);

    int dev = 0, nsm = 148;
    cudaGetDevice(&dev);
    cudaDeviceGetAttribute(&nsm, cudaDevAttrMultiProcessorCount, dev);

    mhc_ws2_kernel<<<nsm, THREADS>>>(x, w, H_pre, H_post, H_res, out, B);
}